// round 1
// baseline (speedup 1.0000x reference)
#include <cuda_runtime.h>
#include <math.h>

#define NROWS 256
#define DDIM  4096
#define CIN   8192
#define HID   4096
#define Y0DIM 512
#define QLAG  64
#define NLAG  129
#define SPLITK 8

// ---------------- scratch (device globals; no allocations allowed) ----------------
__device__ float g_w[NLAG];
__device__ float g_Xc[NROWS * DDIM];
__device__ float g_Y[NROWS * DDIM];
__device__ float g_covp[SPLITK * NROWS * NROWS];
__device__ float g_cov[NROWS * NROWS];
__device__ float g_Z[NROWS * CIN];          // [X | cov@X]
__device__ float g_o1[NROWS * HID];
__device__ float g_o2[NROWS * HID];
__device__ float g_o3[NROWS * HID];

__device__ __forceinline__ float gelu_f(float x) {
    return 0.5f * x * (1.0f + erff(x * 0.70710678118654752440f));
}

// ---------------- 1) weight net: w[l] for lags -64..64 ----------------
__global__ void weight_kernel(const float* __restrict__ w1, const float* __restrict__ b1,
                              const float* __restrict__ w2, const float* __restrict__ b2) {
    int l = threadIdx.x;
    if (l >= NLAG) return;
    float lag = (float)(l - QLAG);
    float acc = b2[0];
    #pragma unroll 8
    for (int j = 0; j < 64; ++j) {
        acc += gelu_f(lag * w1[j] + b1[j]) * w2[j];
    }
    g_w[l] = acc;
}

// ---------------- 2) center rows of X, and copy X into Z[:, :DDIM] ----------------
__global__ void center_kernel(const float* __restrict__ X) {
    int r = blockIdx.x;
    int tid = threadIdx.x;                       // 256 threads
    const float4* xr = (const float4*)(X + (size_t)r * DDIM);
    float4 v[4];
    float s = 0.f;
    #pragma unroll
    for (int i = 0; i < 4; ++i) {
        v[i] = xr[tid + 256 * i];
        s += v[i].x + v[i].y + v[i].z + v[i].w;
    }
    __shared__ float red[256];
    red[tid] = s;
    __syncthreads();
    for (int off = 128; off > 0; off >>= 1) {
        if (tid < off) red[tid] += red[tid + off];
        __syncthreads();
    }
    float mean = red[0] * (1.0f / DDIM);
    float4* xc = (float4*)(g_Xc + (size_t)r * DDIM);
    float4* zz = (float4*)(g_Z + (size_t)r * CIN);
    #pragma unroll
    for (int i = 0; i < 4; ++i) {
        float4 t = v[i];
        zz[tid + 256 * i] = t;                   // z left half = raw X
        t.x -= mean; t.y -= mean; t.z -= mean; t.w -= mean;
        xc[tid + 256 * i] = t;
    }
}

// ---------------- 3) FIR: Y[j,t] = sum_{i=0..128} w[i] * Xc[j, t+i-64] (zero-pad) ----------------
__global__ void fir_kernel() {
    __shared__ float sbuf[DDIM + 2 * QLAG];      // 4224 floats
    __shared__ float ws[NLAG];
    int r = blockIdx.x, tid = threadIdx.x;       // 256 threads
    if (tid < NLAG) ws[tid] = g_w[tid];
    if (tid < QLAG) { sbuf[tid] = 0.f; sbuf[DDIM + QLAG + tid] = 0.f; }
    const float4* xc = (const float4*)(g_Xc + (size_t)r * DDIM);
    #pragma unroll
    for (int i = 0; i < 4; ++i) {
        float4 v = xc[tid + 256 * i];
        *((float4*)&sbuf[QLAG + (tid + 256 * i) * 4]) = v;   // QLAG*4B = 256B aligned
    }
    __syncthreads();
    float acc[16];
    #pragma unroll
    for (int s = 0; s < 16; ++s) acc[s] = 0.f;
    for (int i = 0; i < NLAG; ++i) {
        float wv = ws[i];
        #pragma unroll
        for (int s = 0; s < 16; ++s)
            acc[s] += wv * sbuf[tid + 256 * s + i];          // lanes contiguous: conflict-free
    }
    float* y = g_Y + (size_t)r * DDIM;
    #pragma unroll
    for (int s = 0; s < 16; ++s) y[tid + 256 * s] = acc[s];
}

// ---------------- 4) cov partials: split-K NT GEMM 64x64x16, covp[z] = Xc_chunk @ Y_chunk^T ----------------
__global__ void __launch_bounds__(256) cov_kernel() {
    const int BM = 64, BN = 64, BK = 16, PA = 4;
    __shared__ float As[2][BK][BM + PA];
    __shared__ float Bs[2][BK][BN + PA];
    int tid = threadIdx.x;
    int m0 = blockIdx.y * BM;
    int n0 = blockIdx.x * BN;
    int k0 = blockIdx.z * (DDIM / SPLITK);       // 512-wide K chunk
    int am = tid >> 2;
    int ak = (tid & 3) << 2;
    int ty = tid >> 4, tx = tid & 15;
    const float* Ap = g_Xc + (size_t)(m0 + am) * DDIM + k0 + ak;
    const float* Bp = g_Y  + (size_t)(n0 + am) * DDIM + k0 + ak;

    float acc[4][4];
    #pragma unroll
    for (int i = 0; i < 4; ++i)
        #pragma unroll
        for (int j = 0; j < 4; ++j) acc[i][j] = 0.f;

    float4 ra = *(const float4*)Ap;
    float4 rb = *(const float4*)Bp;
    As[0][ak+0][am]=ra.x; As[0][ak+1][am]=ra.y; As[0][ak+2][am]=ra.z; As[0][ak+3][am]=ra.w;
    Bs[0][ak+0][am]=rb.x; Bs[0][ak+1][am]=rb.y; Bs[0][ak+2][am]=rb.z; Bs[0][ak+3][am]=rb.w;
    __syncthreads();
    const int NKT = (DDIM / SPLITK) / BK;        // 32
    for (int kt = 0; kt < NKT; ++kt) {
        int cur = kt & 1;
        bool more = (kt + 1 < NKT);
        if (more) {
            ra = *(const float4*)(Ap + (kt + 1) * BK);
            rb = *(const float4*)(Bp + (kt + 1) * BK);
        }
        #pragma unroll
        for (int k = 0; k < BK; ++k) {
            float a[4], b[4];
            *(float4*)a = *(const float4*)(&As[cur][k][ty << 2]);
            *(float4*)b = *(const float4*)(&Bs[cur][k][tx << 2]);
            #pragma unroll
            for (int i = 0; i < 4; ++i)
                #pragma unroll
                for (int j = 0; j < 4; ++j) acc[i][j] += a[i] * b[j];
        }
        if (more) {
            int nx = cur ^ 1;
            As[nx][ak+0][am]=ra.x; As[nx][ak+1][am]=ra.y; As[nx][ak+2][am]=ra.z; As[nx][ak+3][am]=ra.w;
            Bs[nx][ak+0][am]=rb.x; Bs[nx][ak+1][am]=rb.y; Bs[nx][ak+2][am]=rb.z; Bs[nx][ak+3][am]=rb.w;
        }
        __syncthreads();
    }
    float* outp = g_covp + (size_t)blockIdx.z * NROWS * NROWS;
    #pragma unroll
    for (int i = 0; i < 4; ++i) {
        float* cp = outp + (size_t)(m0 + (ty << 2) + i) * NROWS + n0 + (tx << 2);
        float4 v = make_float4(acc[i][0], acc[i][1], acc[i][2], acc[i][3]);
        *(float4*)cp = v;
    }
}

__global__ void cov_reduce() {
    int i = blockIdx.x * blockDim.x + threadIdx.x;   // 65536 total
    float s = 0.f;
    #pragma unroll
    for (int z = 0; z < SPLITK; ++z) s += g_covp[z * (NROWS * NROWS) + i];
    g_cov[i] = s * (1.0f / DDIM);
}

// ---------------- generic NT SGEMM: C = f(A[M,K] @ B[N,K]^T + bias), tiles 64x128x16 ----------------
template <bool BIAS, bool GELU>
__global__ void __launch_bounds__(256) gemm_nt(
    const float* __restrict__ A, const float* __restrict__ B,
    float* __restrict__ C, const float* __restrict__ bias,
    int K, int lda, int ldb, int ldc)
{
    const int BM = 64, BN = 128, BK = 16, PA = 4;
    __shared__ float As[2][BK][BM + PA];
    __shared__ float Bs[2][BK][BN + PA];
    int tid = threadIdx.x;
    int m0 = blockIdx.y * BM;
    int n0 = blockIdx.x * BN;
    int am = tid >> 2;
    int ak = (tid & 3) << 2;
    int ty = tid >> 4, tx = tid & 15;
    const float* Ap  = A + (size_t)(m0 + am) * lda + ak;
    const float* Bp  = B + (size_t)(n0 + am) * ldb + ak;
    const float* Bp2 = Bp + (size_t)64 * ldb;

    float acc[4][8];
    #pragma unroll
    for (int i = 0; i < 4; ++i)
        #pragma unroll
        for (int j = 0; j < 8; ++j) acc[i][j] = 0.f;

    float4 ra  = *(const float4*)Ap;
    float4 rb0 = *(const float4*)Bp;
    float4 rb1 = *(const float4*)Bp2;
    As[0][ak+0][am]=ra.x;  As[0][ak+1][am]=ra.y;  As[0][ak+2][am]=ra.z;  As[0][ak+3][am]=ra.w;
    Bs[0][ak+0][am]=rb0.x; Bs[0][ak+1][am]=rb0.y; Bs[0][ak+2][am]=rb0.z; Bs[0][ak+3][am]=rb0.w;
    Bs[0][ak+0][am+64]=rb1.x; Bs[0][ak+1][am+64]=rb1.y; Bs[0][ak+2][am+64]=rb1.z; Bs[0][ak+3][am+64]=rb1.w;
    __syncthreads();

    int NKT = K >> 4;
    for (int kt = 0; kt < NKT; ++kt) {
        int cur = kt & 1;
        bool more = (kt + 1 < NKT);
        if (more) {
            ra  = *(const float4*)(Ap  + (kt + 1) * BK);
            rb0 = *(const float4*)(Bp  + (kt + 1) * BK);
            rb1 = *(const float4*)(Bp2 + (kt + 1) * BK);
        }
        #pragma unroll
        for (int k = 0; k < BK; ++k) {
            float a[4], b[8];
            *(float4*)a       = *(const float4*)(&As[cur][k][ty << 2]);
            *(float4*)b       = *(const float4*)(&Bs[cur][k][tx << 3]);
            *(float4*)(b + 4) = *(const float4*)(&Bs[cur][k][(tx << 3) + 4]);
            #pragma unroll
            for (int i = 0; i < 4; ++i)
                #pragma unroll
                for (int j = 0; j < 8; ++j) acc[i][j] += a[i] * b[j];
        }
        if (more) {
            int nx = cur ^ 1;
            As[nx][ak+0][am]=ra.x;  As[nx][ak+1][am]=ra.y;  As[nx][ak+2][am]=ra.z;  As[nx][ak+3][am]=ra.w;
            Bs[nx][ak+0][am]=rb0.x; Bs[nx][ak+1][am]=rb0.y; Bs[nx][ak+2][am]=rb0.z; Bs[nx][ak+3][am]=rb0.w;
            Bs[nx][ak+0][am+64]=rb1.x; Bs[nx][ak+1][am+64]=rb1.y; Bs[nx][ak+2][am+64]=rb1.z; Bs[nx][ak+3][am+64]=rb1.w;
        }
        __syncthreads();
    }

    float bv[8];
    if (BIAS) {
        *(float4*)bv       = *(const float4*)(bias + n0 + (tx << 3));
        *(float4*)(bv + 4) = *(const float4*)(bias + n0 + (tx << 3) + 4);
    }
    #pragma unroll
    for (int i = 0; i < 4; ++i) {
        float o[8];
        #pragma unroll
        for (int j = 0; j < 8; ++j) {
            float v = acc[i][j];
            if (BIAS) v += bv[j];
            if (GELU) v = gelu_f(v);
            o[j] = v;
        }
        float* cp = C + (size_t)(m0 + (ty << 2) + i) * ldc + n0 + (tx << 3);
        *(float4*)cp       = *(const float4*)o;
        *(float4*)(cp + 4) = *(const float4*)(o + 4);
    }
}

// ---------------- generic NN SGEMM: C = A[M,K] @ B[K,N], tiles 64x128x16 ----------------
__global__ void __launch_bounds__(256) gemm_nn(
    const float* __restrict__ A, const float* __restrict__ B,
    float* __restrict__ C, int K, int lda, int ldb, int ldc)
{
    const int BM = 64, BN = 128, BK = 16, PA = 4;
    __shared__ float As[2][BK][BM + PA];
    __shared__ float Bs[2][BK][BN + PA];
    int tid = threadIdx.x;
    int m0 = blockIdx.y * BM;
    int n0 = blockIdx.x * BN;
    int am = tid >> 2;
    int ak = (tid & 3) << 2;
    int br = tid >> 5;                 // 0..7
    int bc = (tid & 31) << 2;          // 0..124
    int ty = tid >> 4, tx = tid & 15;
    const float* Ap = A + (size_t)(m0 + am) * lda + ak;
    const float* Bp = B + (size_t)br * ldb + n0 + bc;

    float acc[4][8];
    #pragma unroll
    for (int i = 0; i < 4; ++i)
        #pragma unroll
        for (int j = 0; j < 8; ++j) acc[i][j] = 0.f;

    float4 ra  = *(const float4*)Ap;
    float4 rb0 = *(const float4*)Bp;
    float4 rb1 = *(const float4*)(Bp + (size_t)8 * ldb);
    As[0][ak+0][am]=ra.x; As[0][ak+1][am]=ra.y; As[0][ak+2][am]=ra.z; As[0][ak+3][am]=ra.w;
    *(float4*)(&Bs[0][br][bc])     = rb0;
    *(float4*)(&Bs[0][br + 8][bc]) = rb1;
    __syncthreads();

    int NKT = K >> 4;
    for (int kt = 0; kt < NKT; ++kt) {
        int cur = kt & 1;
        bool more = (kt + 1 < NKT);
        if (more) {
            ra  = *(const float4*)(Ap + (kt + 1) * BK);
            rb0 = *(const float4*)(Bp + (size_t)((kt + 1) * BK) * ldb);
            rb1 = *(const float4*)(Bp + (size_t)((kt + 1) * BK + 8) * ldb);
        }
        #pragma unroll
        for (int k = 0; k < BK; ++k) {
            float a[4], b[8];
            *(float4*)a       = *(const float4*)(&As[cur][k][ty << 2]);
            *(float4*)b       = *(const float4*)(&Bs[cur][k][tx << 3]);
            *(float4*)(b + 4) = *(const float4*)(&Bs[cur][k][(tx << 3) + 4]);
            #pragma unroll
            for (int i = 0; i < 4; ++i)
                #pragma unroll
                for (int j = 0; j < 8; ++j) acc[i][j] += a[i] * b[j];
        }
        if (more) {
            int nx = cur ^ 1;
            As[nx][ak+0][am]=ra.x; As[nx][ak+1][am]=ra.y; As[nx][ak+2][am]=ra.z; As[nx][ak+3][am]=ra.w;
            *(float4*)(&Bs[nx][br][bc])     = rb0;
            *(float4*)(&Bs[nx][br + 8][bc]) = rb1;
        }
        __syncthreads();
    }

    #pragma unroll
    for (int i = 0; i < 4; ++i) {
        float* cp = C + (size_t)(m0 + (ty << 2) + i) * ldc + n0 + (tx << 3);
        float4 v0 = make_float4(acc[i][0], acc[i][1], acc[i][2], acc[i][3]);
        float4 v1 = make_float4(acc[i][4], acc[i][5], acc[i][6], acc[i][7]);
        *(float4*)cp       = v0;
        *(float4*)(cp + 4) = v1;
    }
}

// ---------------- launch ----------------
extern "C" void kernel_launch(void* const* d_in, const int* in_sizes, int n_in,
                              void* d_out, int out_size) {
    const float* X     = (const float*)d_in[0];
    const float* wn_w1 = (const float*)d_in[1];
    const float* wn_b1 = (const float*)d_in[2];
    const float* wn_w2 = (const float*)d_in[3];
    const float* wn_b2 = (const float*)d_in[4];
    const float* fc1_w = (const float*)d_in[5];
    const float* fc1_b = (const float*)d_in[6];
    const float* fc2_w = (const float*)d_in[7];
    const float* fc2_b = (const float*)d_in[8];
    const float* fc3_w = (const float*)d_in[9];
    const float* fc3_b = (const float*)d_in[10];
    const float* proj  = (const float*)d_in[11];
    float* out = (float*)d_out;

    float *pZ, *pcov, *po1, *po2, *po3;
    cudaGetSymbolAddress((void**)&pZ,   g_Z);
    cudaGetSymbolAddress((void**)&pcov, g_cov);
    cudaGetSymbolAddress((void**)&po1,  g_o1);
    cudaGetSymbolAddress((void**)&po2,  g_o2);
    cudaGetSymbolAddress((void**)&po3,  g_o3);

    weight_kernel<<<1, NLAG>>>(wn_w1, wn_b1, wn_w2, wn_b2);
    center_kernel<<<NROWS, 256>>>(X);
    fir_kernel<<<NROWS, 256>>>();
    cov_kernel<<<dim3(NROWS / 64, NROWS / 64, SPLITK), 256>>>();
    cov_reduce<<<(NROWS * NROWS) / 256, 256>>>();

    // cov_inter = cov @ X  -> Z[:, DDIM:]
    gemm_nn<<<dim3(DDIM / 128, NROWS / 64), 256>>>(pcov, X, pZ + DDIM, NROWS, NROWS, DDIM, CIN);
    // fc1: gelu(Z @ fc1_w^T + b)
    gemm_nt<true, true ><<<dim3(HID / 128, NROWS / 64), 256>>>(pZ,  fc1_w, po1, fc1_b, CIN, CIN, CIN, HID);
    // fc2: gelu(o1 @ fc2_w^T + b)
    gemm_nt<true, true ><<<dim3(HID / 128, NROWS / 64), 256>>>(po1, fc2_w, po2, fc2_b, HID, HID, HID, HID);
    // fc3: o2 @ fc3_w^T + b
    gemm_nt<true, false><<<dim3(HID / 128, NROWS / 64), 256>>>(po2, fc3_w, po3, fc3_b, HID, HID, HID, HID);
    // out = proj @ o3
    gemm_nn<<<dim3(HID / 128, Y0DIM / 64), 256>>>(proj, po3, out, NROWS, NROWS, HID, HID);
}

// round 3
// speedup vs baseline: 1.2824x; 1.2824x over previous
#include <cuda_runtime.h>
#include <cuda_bf16.h>
#include <math.h>
#include <cstdint>

#define NROWS 256
#define DDIM  4096
#define CIN   8192
#define HID   4096
#define Y0DIM 512
#define QLAG  64
#define NLAG  129
#define SPLITK 8

// ---------------- scratch (device globals; no allocations allowed) ----------------
__device__ float g_w[NLAG];
__device__ float g_Xc[NROWS * DDIM];
__device__ float g_Y[NROWS * DDIM];
__device__ float g_Xt[DDIM * NROWS];
__device__ float g_covp[SPLITK * NROWS * NROWS];
__device__ float g_cov[NROWS * NROWS];
__device__ float g_Z[NROWS * CIN];          // [X | cov@X]
__device__ float g_o1[NROWS * HID];
__device__ float g_o2[NROWS * HID];
__device__ float g_o3t[HID * NROWS];        // fc3 output, transposed [N, M]

__device__ __forceinline__ float gelu_f(float x) {
    return 0.5f * x * (1.0f + erff(x * 0.70710678118654752440f));
}

__device__ __forceinline__ uint32_t smem_u32(const void* p) {
    uint32_t a;
    asm("{ .reg .u64 t; cvta.to.shared.u64 t, %1; cvt.u32.u64 %0, t; }" : "=r"(a) : "l"(p));
    return a;
}
__device__ __forceinline__ void ldsm4(uint32_t* r, uint32_t addr) {
    asm volatile("ldmatrix.sync.aligned.m8n8.x4.shared.b16 {%0,%1,%2,%3}, [%4];"
        : "=r"(r[0]), "=r"(r[1]), "=r"(r[2]), "=r"(r[3]) : "r"(addr));
}
__device__ __forceinline__ void mma16816(float* c, const uint32_t* a, const uint32_t* b) {
    asm volatile(
        "mma.sync.aligned.m16n8k16.row.col.f32.bf16.bf16.f32 "
        "{%0,%1,%2,%3}, {%4,%5,%6,%7}, {%8,%9}, {%0,%1,%2,%3};"
        : "+f"(c[0]), "+f"(c[1]), "+f"(c[2]), "+f"(c[3])
        : "r"(a[0]), "r"(a[1]), "r"(a[2]), "r"(a[3]), "r"(b[0]), "r"(b[1]));
}
__device__ __forceinline__ uint32_t pack_bf(float a, float b) {
    __nv_bfloat162 t;
    t.x = __float2bfloat16(a);
    t.y = __float2bfloat16(b);
    return *reinterpret_cast<uint32_t*>(&t);
}
__device__ __forceinline__ float bf_hi(float x) {
    return __bfloat162float(__float2bfloat16(x));
}
__device__ __forceinline__ uint32_t swz(uint32_t off) {
    return off ^ ((off >> 3) & 0x30);
}

// ====================== HMMA bf16 3-split NT GEMM ======================
// C[M,N] = op(A[M,K] @ B[N,K]^T + bias), fp32 in/out.
// Each fp32 x = hi + lo (bf16 each); dot = hh + lh + hl (drop ll, ~2^-18).
// Tiles: BM=64, BN=128, K chunk = 16 fp32. Stage row: [hi(32B) | lo(32B)] = 64B.
template <bool BIAS, bool GELU, bool TRANSOUT>
__global__ void __launch_bounds__(256) hmma_gemm(
    const float* __restrict__ A, const float* __restrict__ B,
    float* __restrict__ C, const float* __restrict__ bias,
    int K, int lda, int ldb, int ldc)
{
    __shared__ __align__(1024) char smem_raw[34048];  // stages 24KB / epilogue 64*129*4
    const uint32_t sb = smem_u32(smem_raw);
    const int tid = threadIdx.x;
    const int lane = tid & 31, wid = tid >> 5;
    const int warp_m = wid >> 2, warp_n = wid & 3;    // 2 x 4 warps, warp tile 32x32
    const int m0 = blockIdx.y * 64, n0 = blockIdx.x * 128;

    // global-load coords
    const int arow = tid >> 2, ac4 = tid & 3;         // A: 64 rows x 16 floats
    const int brow = tid >> 1, bq  = tid & 1;         // B: 128 rows x 16 floats
    const float* Ap = A + (size_t)(m0 + arow) * lda + ac4 * 4;
    const float* Bp = B + (size_t)(n0 + brow) * ldb + bq * 8;

    const uint32_t offA = (uint32_t)arow * 64 + ac4 * 8;
    const uint32_t offB = (uint32_t)brow * 64 + bq * 16;

    // ldmatrix stage-relative swizzled offsets
    uint32_t aoff[2][2], boff[2][2];                  // [frag/pair][step]
    #pragma unroll
    for (int f = 0; f < 2; ++f)
        #pragma unroll
        for (int s = 0; s < 2; ++s) {
            int rowA = warp_m * 32 + f * 16 + (lane & 15);
            aoff[f][s] = swz((uint32_t)rowA * 64 + s * 32 + ((lane >> 4) << 4));
            int rowB = warp_n * 32 + f * 16 + (((lane >> 4) & 1) << 3) + (lane & 7);
            boff[f][s] = swz((uint32_t)rowB * 64 + s * 32 + (((lane >> 3) & 1) << 4));
        }

    float acc[2][4][4];
    #pragma unroll
    for (int i = 0; i < 2; ++i)
        #pragma unroll
        for (int j = 0; j < 4; ++j)
            #pragma unroll
            for (int r = 0; r < 4; ++r) acc[i][j][r] = 0.f;

    const int NC = K >> 4;
    float4 bufA[2];
    float4 bufB[2][2];
    bufA[0]    = *(const float4*)(Ap);
    bufB[0][0] = *(const float4*)(Bp);
    bufB[0][1] = *(const float4*)(Bp + 4);
    bufA[1]    = *(const float4*)(Ap + 16);
    bufB[1][0] = *(const float4*)(Bp + 16);
    bufB[1][1] = *(const float4*)(Bp + 20);

    for (int i = 0; i < NC; ++i) {
        const int s = i & 1;
        char* stA = smem_raw + s * 4096;
        char* stB = smem_raw + 8192 + s * 8192;
        // ---- convert + STS chunk i ----
        {
            float4 v = bufA[s];
            float hx = bf_hi(v.x), hy = bf_hi(v.y), hz = bf_hi(v.z), hw = bf_hi(v.w);
            *(uint2*)(stA + swz(offA))      = make_uint2(pack_bf(hx, hy), pack_bf(hz, hw));
            *(uint2*)(stA + swz(offA + 32)) = make_uint2(pack_bf(v.x - hx, v.y - hy),
                                                         pack_bf(v.z - hz, v.w - hw));
            #pragma unroll
            for (int fq = 0; fq < 2; ++fq) {
                float4 w = bufB[s][fq];
                float ax = bf_hi(w.x), ay = bf_hi(w.y), az = bf_hi(w.z), aw = bf_hi(w.w);
                uint32_t ob = offB + fq * 8;
                *(uint2*)(stB + swz(ob))      = make_uint2(pack_bf(ax, ay), pack_bf(az, aw));
                *(uint2*)(stB + swz(ob + 32)) = make_uint2(pack_bf(w.x - ax, w.y - ay),
                                                           pack_bf(w.z - az, w.w - aw));
            }
        }
        // ---- prefetch chunk i+2 ----
        if (i + 2 < NC) {
            bufA[s]    = *(const float4*)(Ap + (i + 2) * 16);
            bufB[s][0] = *(const float4*)(Bp + (i + 2) * 16);
            bufB[s][1] = *(const float4*)(Bp + (i + 2) * 16 + 4);
        }
        __syncthreads();
        // ---- compute on stage s ----
        uint32_t baseA = sb + s * 4096;
        uint32_t baseB = sb + 8192 + s * 8192;
        uint32_t af[2][2][4], bfr[2][4][2];
        #pragma unroll
        for (int st = 0; st < 2; ++st) {
            #pragma unroll
            for (int f = 0; f < 2; ++f) ldsm4(af[st][f], baseA + aoff[f][st]);
            #pragma unroll
            for (int p = 0; p < 2; ++p) {
                uint32_t t[4];
                ldsm4(t, baseB + boff[p][st]);
                bfr[st][2 * p][0] = t[0]; bfr[st][2 * p][1] = t[1];
                bfr[st][2 * p + 1][0] = t[2]; bfr[st][2 * p + 1][1] = t[3];
            }
        }
        #pragma unroll
        for (int i2 = 0; i2 < 2; ++i2)
            #pragma unroll
            for (int j = 0; j < 4; ++j) {
                mma16816(acc[i2][j], af[0][i2], bfr[0][j]);   // hh
                mma16816(acc[i2][j], af[1][i2], bfr[0][j]);   // lh
                mma16816(acc[i2][j], af[0][i2], bfr[1][j]);   // hl
            }
        __syncthreads();
    }

    // ---- epilogue: stage to smem, coalesced write ----
    float* so = (float*)smem_raw;                     // 64 x 129
    #pragma unroll
    for (int i2 = 0; i2 < 2; ++i2)
        #pragma unroll
        for (int j = 0; j < 4; ++j)
            #pragma unroll
            for (int r = 0; r < 4; ++r) {
                int row = warp_m * 32 + i2 * 16 + (lane >> 2) + ((r >> 1) << 3);
                int col = warp_n * 32 + j * 8 + ((lane & 3) << 1) + (r & 1);
                so[row * 129 + col] = acc[i2][j][r];
            }
    __syncthreads();

    if (!TRANSOUT) {
        #pragma unroll
        for (int it = 0; it < 8; ++it) {
            int idx = tid + 256 * it;
            int row = idx >> 5, q = idx & 31;
            float o[4];
            #pragma unroll
            for (int u = 0; u < 4; ++u) {
                float v = so[row * 129 + q * 4 + u];
                if (BIAS) v += __ldg(bias + n0 + q * 4 + u);
                if (GELU) v = gelu_f(v);
                o[u] = v;
            }
            *(float4*)(C + (size_t)(m0 + row) * ldc + n0 + q * 4) = *(const float4*)o;
        }
    } else {
        #pragma unroll
        for (int it = 0; it < 8; ++it) {
            int idx = tid + 256 * it;
            int n = idx >> 4, q = idx & 15;
            float bv = BIAS ? __ldg(bias + n0 + n) : 0.f;
            float o[4];
            #pragma unroll
            for (int u = 0; u < 4; ++u) {
                float v = so[(q * 4 + u) * 129 + n] + bv;
                if (GELU) v = gelu_f(v);
                o[u] = v;
            }
            *(float4*)(C + (size_t)(n0 + n) * ldc + m0 + q * 4) = *(const float4*)o;
        }
    }
}

// ---------------- 1) weight net ----------------
__global__ void weight_kernel(const float* __restrict__ w1, const float* __restrict__ b1,
                              const float* __restrict__ w2, const float* __restrict__ b2) {
    int l = threadIdx.x;
    if (l >= NLAG) return;
    float lag = (float)(l - QLAG);
    float acc = b2[0];
    #pragma unroll 8
    for (int j = 0; j < 64; ++j) acc += gelu_f(lag * w1[j] + b1[j]) * w2[j];
    g_w[l] = acc;
}

// ---------------- 2) center rows; copy X into Z left half ----------------
__global__ void center_kernel(const float* __restrict__ X) {
    int r = blockIdx.x, tid = threadIdx.x;
    const float4* xr = (const float4*)(X + (size_t)r * DDIM);
    float4 v[4]; float s = 0.f;
    #pragma unroll
    for (int i = 0; i < 4; ++i) {
        v[i] = xr[tid + 256 * i];
        s += v[i].x + v[i].y + v[i].z + v[i].w;
    }
    __shared__ float red[256];
    red[tid] = s; __syncthreads();
    for (int off = 128; off > 0; off >>= 1) {
        if (tid < off) red[tid] += red[tid + off];
        __syncthreads();
    }
    float mean = red[0] * (1.0f / DDIM);
    float4* xc = (float4*)(g_Xc + (size_t)r * DDIM);
    float4* zz = (float4*)(g_Z + (size_t)r * CIN);
    #pragma unroll
    for (int i = 0; i < 4; ++i) {
        float4 t = v[i];
        zz[tid + 256 * i] = t;
        t.x -= mean; t.y -= mean; t.z -= mean; t.w -= mean;
        xc[tid + 256 * i] = t;
    }
}

// ---------------- transpose X -> Xt[4096,256] ----------------
__global__ void transpose_kernel(const float* __restrict__ X, float* __restrict__ XT) {
    __shared__ float t[32][33];
    int bx = blockIdx.x * 32;
    int by = blockIdx.y * 32;
    int x = threadIdx.x, y = threadIdx.y;
    #pragma unroll
    for (int j = 0; j < 32; j += 8)
        t[y + j][x] = X[(size_t)(by + y + j) * DDIM + bx + x];
    __syncthreads();
    #pragma unroll
    for (int j = 0; j < 32; j += 8)
        XT[(size_t)(bx + y + j) * NROWS + by + x] = t[x][y + j];
}

// ---------------- 3) FIR ----------------
__global__ void fir_kernel() {
    __shared__ float sbuf[DDIM + 2 * QLAG];
    __shared__ float ws[NLAG];
    int r = blockIdx.x, tid = threadIdx.x;
    if (tid < NLAG) ws[tid] = g_w[tid];
    if (tid < QLAG) { sbuf[tid] = 0.f; sbuf[DDIM + QLAG + tid] = 0.f; }
    const float4* xc = (const float4*)(g_Xc + (size_t)r * DDIM);
    #pragma unroll
    for (int i = 0; i < 4; ++i) {
        float4 v = xc[tid + 256 * i];
        *((float4*)&sbuf[QLAG + (tid + 256 * i) * 4]) = v;
    }
    __syncthreads();
    float acc[16];
    #pragma unroll
    for (int s = 0; s < 16; ++s) acc[s] = 0.f;
    for (int i = 0; i < NLAG; ++i) {
        float wv = ws[i];
        #pragma unroll
        for (int s = 0; s < 16; ++s) acc[s] += wv * sbuf[tid + 256 * s + i];
    }
    float* y = g_Y + (size_t)r * DDIM;
    #pragma unroll
    for (int s = 0; s < 16; ++s) y[tid + 256 * s] = acc[s];
}

// ---------------- 4) cov partials (fp32 split-K) ----------------
__global__ void __launch_bounds__(256) cov_kernel() {
    const int BM = 64, BN = 64, BK = 16, PA = 4;
    __shared__ float As[2][BK][BM + PA];
    __shared__ float Bs[2][BK][BN + PA];
    int tid = threadIdx.x;
    int m0 = blockIdx.y * BM, n0 = blockIdx.x * BN;
    int k0 = blockIdx.z * (DDIM / SPLITK);
    int am = tid >> 2, ak = (tid & 3) << 2;
    int ty = tid >> 4, tx = tid & 15;
    const float* Ap = g_Xc + (size_t)(m0 + am) * DDIM + k0 + ak;
    const float* Bp = g_Y  + (size_t)(n0 + am) * DDIM + k0 + ak;
    float acc[4][4];
    #pragma unroll
    for (int i = 0; i < 4; ++i)
        #pragma unroll
        for (int j = 0; j < 4; ++j) acc[i][j] = 0.f;
    float4 ra = *(const float4*)Ap, rb = *(const float4*)Bp;
    As[0][ak+0][am]=ra.x; As[0][ak+1][am]=ra.y; As[0][ak+2][am]=ra.z; As[0][ak+3][am]=ra.w;
    Bs[0][ak+0][am]=rb.x; Bs[0][ak+1][am]=rb.y; Bs[0][ak+2][am]=rb.z; Bs[0][ak+3][am]=rb.w;
    __syncthreads();
    const int NKT = (DDIM / SPLITK) / BK;
    for (int kt = 0; kt < NKT; ++kt) {
        int cur = kt & 1;
        bool more = (kt + 1 < NKT);
        if (more) { ra = *(const float4*)(Ap + (kt+1)*BK); rb = *(const float4*)(Bp + (kt+1)*BK); }
        #pragma unroll
        for (int k = 0; k < BK; ++k) {
            float a[4], b[4];
            *(float4*)a = *(const float4*)(&As[cur][k][ty << 2]);
            *(float4*)b = *(const float4*)(&Bs[cur][k][tx << 2]);
            #pragma unroll
            for (int i = 0; i < 4; ++i)
                #pragma unroll
                for (int j = 0; j < 4; ++j) acc[i][j] += a[i] * b[j];
        }
        if (more) {
            int nx = cur ^ 1;
            As[nx][ak+0][am]=ra.x; As[nx][ak+1][am]=ra.y; As[nx][ak+2][am]=ra.z; As[nx][ak+3][am]=ra.w;
            Bs[nx][ak+0][am]=rb.x; Bs[nx][ak+1][am]=rb.y; Bs[nx][ak+2][am]=rb.z; Bs[nx][ak+3][am]=rb.w;
        }
        __syncthreads();
    }
    float* outp = g_covp + (size_t)blockIdx.z * NROWS * NROWS;
    #pragma unroll
    for (int i = 0; i < 4; ++i) {
        float* cp = outp + (size_t)(m0 + (ty << 2) + i) * NROWS + n0 + (tx << 2);
        *(float4*)cp = make_float4(acc[i][0], acc[i][1], acc[i][2], acc[i][3]);
    }
}

__global__ void cov_reduce() {
    int i = blockIdx.x * blockDim.x + threadIdx.x;
    float s = 0.f;
    #pragma unroll
    for (int z = 0; z < SPLITK; ++z) s += g_covp[z * (NROWS * NROWS) + i];
    g_cov[i] = s * (1.0f / DDIM);
}

// ---------------- launch ----------------
extern "C" void kernel_launch(void* const* d_in, const int* in_sizes, int n_in,
                              void* d_out, int out_size) {
    const float* X     = (const float*)d_in[0];
    const float* wn_w1 = (const float*)d_in[1];
    const float* wn_b1 = (const float*)d_in[2];
    const float* wn_w2 = (const float*)d_in[3];
    const float* wn_b2 = (const float*)d_in[4];
    const float* fc1_w = (const float*)d_in[5];
    const float* fc1_b = (const float*)d_in[6];
    const float* fc2_w = (const float*)d_in[7];
    const float* fc2_b = (const float*)d_in[8];
    const float* fc3_w = (const float*)d_in[9];
    const float* fc3_b = (const float*)d_in[10];
    const float* proj  = (const float*)d_in[11];
    float* out = (float*)d_out;

    float *pZ, *pcov, *po1, *po2, *po3t, *pXt;
    cudaGetSymbolAddress((void**)&pZ,   g_Z);
    cudaGetSymbolAddress((void**)&pcov, g_cov);
    cudaGetSymbolAddress((void**)&po1,  g_o1);
    cudaGetSymbolAddress((void**)&po2,  g_o2);
    cudaGetSymbolAddress((void**)&po3t, g_o3t);
    cudaGetSymbolAddress((void**)&pXt,  g_Xt);

    weight_kernel<<<1, NLAG>>>(wn_w1, wn_b1, wn_w2, wn_b2);
    center_kernel<<<NROWS, 256>>>(X);
    transpose_kernel<<<dim3(DDIM / 32, NROWS / 32), dim3(32, 8)>>>(X, pXt);
    fir_kernel<<<NROWS, 256>>>();
    cov_kernel<<<dim3(NROWS / 64, NROWS / 64, SPLITK), 256>>>();
    cov_reduce<<<(NROWS * NROWS) / 256, 256>>>();

    // cov_inter = cov @ X  (NT with B = X^T) -> Z[:, DDIM:]
    hmma_gemm<false, false, false><<<dim3(DDIM / 128, NROWS / 64), 256>>>(
        pcov, pXt, pZ + DDIM, nullptr, NROWS, NROWS, NROWS, CIN);
    // fc1: gelu(Z @ fc1_w^T + b)
    hmma_gemm<true, true, false><<<dim3(HID / 128, NROWS / 64), 256>>>(
        pZ, fc1_w, po1, fc1_b, CIN, CIN, CIN, HID);
    // fc2: gelu(o1 @ fc2_w^T + b)
    hmma_gemm<true, true, false><<<dim3(HID / 128, NROWS / 64), 256>>>(
        po1, fc2_w, po2, fc2_b, HID, HID, HID, HID);
    // fc3: o2 @ fc3_w^T + b -> o3t[4096, 256] (transposed)
    hmma_gemm<true, false, true><<<dim3(HID / 128, NROWS / 64), 256>>>(
        po2, fc3_w, po3t, fc3_b, HID, HID, HID, NROWS);
    // out = proj @ o3  (NT: A=proj[512,256], B=o3t[4096,256])
    hmma_gemm<false, false, false><<<dim3(HID / 128, Y0DIM / 64), 256>>>(
        proj, po3t, out, nullptr, NROWS, NROWS, NROWS, HID);
}

// round 4
// speedup vs baseline: 1.5958x; 1.2443x over previous
#include <cuda_runtime.h>
#include <cuda_bf16.h>
#include <math.h>
#include <cstdint>

#define NROWS 256
#define DDIM  4096
#define CIN   8192
#define HID   4096
#define Y0DIM 512
#define QLAG  64
#define NLAG  129
#define SPLITK 8

// ---------------- scratch (device globals; no allocations allowed) ----------------
__device__ float g_w[NLAG];
__device__ float g_Xc[NROWS * DDIM];
__device__ float g_Y[NROWS * DDIM];
__device__ float g_Xt[DDIM * NROWS];
__device__ float g_covp[SPLITK * NROWS * NROWS];
__device__ float g_cov[NROWS * NROWS];
__device__ float g_Z[NROWS * CIN];          // [X | cov@X]
__device__ float g_o1[NROWS * HID];
__device__ float g_o2[NROWS * HID];
__device__ float g_o3t[HID * NROWS];        // fc3 output, transposed [N, M]

__device__ __forceinline__ float gelu_f(float x) {
    return 0.5f * x * (1.0f + erff(x * 0.70710678118654752440f));
}
__device__ __forceinline__ uint32_t smem_u32(const void* p) {
    uint32_t a;
    asm("{ .reg .u64 t; cvta.to.shared.u64 t, %1; cvt.u32.u64 %0, t; }" : "=r"(a) : "l"(p));
    return a;
}
__device__ __forceinline__ void ldsm4(uint32_t* r, uint32_t addr) {
    asm volatile("ldmatrix.sync.aligned.m8n8.x4.shared.b16 {%0,%1,%2,%3}, [%4];"
        : "=r"(r[0]), "=r"(r[1]), "=r"(r[2]), "=r"(r[3]) : "r"(addr));
}
__device__ __forceinline__ void mma16816(float* c, const uint32_t* a, const uint32_t* b) {
    asm volatile(
        "mma.sync.aligned.m16n8k16.row.col.f32.bf16.bf16.f32 "
        "{%0,%1,%2,%3}, {%4,%5,%6,%7}, {%8,%9}, {%0,%1,%2,%3};"
        : "+f"(c[0]), "+f"(c[1]), "+f"(c[2]), "+f"(c[3])
        : "r"(a[0]), "r"(a[1]), "r"(a[2]), "r"(a[3]), "r"(b[0]), "r"(b[1]));
}
__device__ __forceinline__ uint32_t pack_bf(float a, float b) {
    __nv_bfloat162 t;
    t.x = __float2bfloat16(a);
    t.y = __float2bfloat16(b);
    return *reinterpret_cast<uint32_t*>(&t);
}
__device__ __forceinline__ float bf_hi(float x) {
    return __bfloat162float(__float2bfloat16(x));
}
// 128B-row phase swizzle: 16B unit ^= row%8
__device__ __forceinline__ uint32_t swz(uint32_t off) {
    return off ^ (((off >> 7) & 7) << 4);
}

// ====================== HMMA bf16 3-split NT GEMM ======================
// C[M,N] = op(A[M,K] @ B[N,K]^T + bias), fp32 in/out.
// x = hi + lo (bf16 each); dot = hh + lh + hl (drop ll, ~2^-18).
// BM=64, BN=128, K chunk = 32 fp32. Stage row (128B): [hi k0..31 | lo k0..31].
// Single __syncthreads per chunk; STS(next) overlapped with compute(cur).
#define KC 32
#define A_STG 8192
#define B_STG 16384

template <bool BIAS, bool GELU, bool TRANSOUT>
__global__ void __launch_bounds__(256) hmma_gemm(
    const float* __restrict__ A, const float* __restrict__ B,
    float* __restrict__ C, const float* __restrict__ bias,
    int K, int lda, int ldb, int ldc)
{
    __shared__ __align__(1024) char sm[49152];   // A:0,8K  B:16K,32K
    const uint32_t sb = smem_u32(sm);
    const int tid = threadIdx.x;
    const int lane = tid & 31, wid = tid >> 5;
    const int warp_m = wid >> 2, warp_n = wid & 3;     // 2 x 4 warps, tile 32x32
    const int m0 = blockIdx.y * 64, n0 = blockIdx.x * 128;

    // global-load coords (chunk = 32 floats)
    const int arow = tid >> 2, ac = (tid & 3) * 8;     // A: 64 rows, 8 floats/thr
    const int brow = tid >> 1, bc = (tid & 1) * 16;    // B: 128 rows, 16 floats/thr
    const float* Ap = A + (size_t)(m0 + arow) * lda + ac;
    const float* Bp = B + (size_t)(n0 + brow) * ldb + bc;

    const uint32_t offA_hi = swz((uint32_t)arow * 128 + ac * 2);
    const uint32_t offA_lo = swz((uint32_t)arow * 128 + ac * 2 + 64);
    const uint32_t offB_hi0 = swz((uint32_t)brow * 128 + bc * 2);
    const uint32_t offB_hi1 = swz((uint32_t)brow * 128 + bc * 2 + 16);
    const uint32_t offB_lo0 = swz((uint32_t)brow * 128 + bc * 2 + 64);
    const uint32_t offB_lo1 = swz((uint32_t)brow * 128 + bc * 2 + 80);

    // ldmatrix offsets: [plane][kstep][frag]
    uint32_t aoff[2][2][2], boff[2][2][2];
    #pragma unroll
    for (int p = 0; p < 2; ++p)
        #pragma unroll
        for (int s = 0; s < 2; ++s) {
            #pragma unroll
            for (int f = 0; f < 2; ++f) {
                int rowA = warp_m * 32 + f * 16 + (lane & 15);
                aoff[p][s][f] = swz((uint32_t)rowA * 128 + p * 64 + s * 32 + ((lane >> 4) << 4));
                int rowB = warp_n * 32 + f * 16 + (((lane >> 4) & 1) << 3) + (lane & 7);
                boff[p][s][f] = swz((uint32_t)rowB * 128 + p * 64 + s * 32 + (((lane >> 3) & 1) << 4));
            }
        }

    float acc[2][4][4];
    #pragma unroll
    for (int i = 0; i < 2; ++i)
        #pragma unroll
        for (int j = 0; j < 4; ++j)
            #pragma unroll
            for (int r = 0; r < 4; ++r) acc[i][j][r] = 0.f;

    const int NC = K >> 5;

    float4 bufA[2][2], bufB[2][4];
    // prologue: load chunk0, STS stage0, load chunk1
    #pragma unroll
    for (int q = 0; q < 2; ++q) bufA[0][q] = *(const float4*)(Ap + q * 4);
    #pragma unroll
    for (int q = 0; q < 4; ++q) bufB[0][q] = *(const float4*)(Bp + q * 4);
    {
        char* stA = sm + 0;
        char* stB = sm + 16384;
        float f[8];
        *(float4*)f = bufA[0][0]; *(float4*)(f + 4) = bufA[0][1];
        float h[8];
        #pragma unroll
        for (int u = 0; u < 8; ++u) h[u] = bf_hi(f[u]);
        *(uint4*)(stA + offA_hi) = make_uint4(pack_bf(h[0],h[1]),pack_bf(h[2],h[3]),pack_bf(h[4],h[5]),pack_bf(h[6],h[7]));
        *(uint4*)(stA + offA_lo) = make_uint4(pack_bf(f[0]-h[0],f[1]-h[1]),pack_bf(f[2]-h[2],f[3]-h[3]),
                                              pack_bf(f[4]-h[4],f[5]-h[5]),pack_bf(f[6]-h[6],f[7]-h[7]));
        float g[16], gh[16];
        #pragma unroll
        for (int q = 0; q < 4; ++q) *(float4*)(g + 4 * q) = bufB[0][q];
        #pragma unroll
        for (int u = 0; u < 16; ++u) gh[u] = bf_hi(g[u]);
        *(uint4*)(stB + offB_hi0) = make_uint4(pack_bf(gh[0],gh[1]),pack_bf(gh[2],gh[3]),pack_bf(gh[4],gh[5]),pack_bf(gh[6],gh[7]));
        *(uint4*)(stB + offB_hi1) = make_uint4(pack_bf(gh[8],gh[9]),pack_bf(gh[10],gh[11]),pack_bf(gh[12],gh[13]),pack_bf(gh[14],gh[15]));
        *(uint4*)(stB + offB_lo0) = make_uint4(pack_bf(g[0]-gh[0],g[1]-gh[1]),pack_bf(g[2]-gh[2],g[3]-gh[3]),
                                               pack_bf(g[4]-gh[4],g[5]-gh[5]),pack_bf(g[6]-gh[6],g[7]-gh[7]));
        *(uint4*)(stB + offB_lo1) = make_uint4(pack_bf(g[8]-gh[8],g[9]-gh[9]),pack_bf(g[10]-gh[10],g[11]-gh[11]),
                                               pack_bf(g[12]-gh[12],g[13]-gh[13]),pack_bf(g[14]-gh[14],g[15]-gh[15]));
    }
    if (NC > 1) {
        #pragma unroll
        for (int q = 0; q < 2; ++q) bufA[1][q] = *(const float4*)(Ap + KC + q * 4);
        #pragma unroll
        for (int q = 0; q < 4; ++q) bufB[1][q] = *(const float4*)(Bp + KC + q * 4);
    }
    __syncthreads();

    for (int i = 0; i < NC; ++i) {
        const int cur = i & 1;
        const int nxt = cur ^ 1;
        // ---- STS chunk i+1 into stage nxt (overlaps with compute below) ----
        if (i + 1 < NC) {
            char* stA = sm + nxt * A_STG;
            char* stB = sm + 16384 + nxt * B_STG;
            float f[8];
            *(float4*)f = bufA[nxt][0]; *(float4*)(f + 4) = bufA[nxt][1];
            float h[8];
            #pragma unroll
            for (int u = 0; u < 8; ++u) h[u] = bf_hi(f[u]);
            *(uint4*)(stA + offA_hi) = make_uint4(pack_bf(h[0],h[1]),pack_bf(h[2],h[3]),pack_bf(h[4],h[5]),pack_bf(h[6],h[7]));
            *(uint4*)(stA + offA_lo) = make_uint4(pack_bf(f[0]-h[0],f[1]-h[1]),pack_bf(f[2]-h[2],f[3]-h[3]),
                                                  pack_bf(f[4]-h[4],f[5]-h[5]),pack_bf(f[6]-h[6],f[7]-h[7]));
            float g[16], gh[16];
            #pragma unroll
            for (int q = 0; q < 4; ++q) *(float4*)(g + 4 * q) = bufB[nxt][q];
            #pragma unroll
            for (int u = 0; u < 16; ++u) gh[u] = bf_hi(g[u]);
            *(uint4*)(stB + offB_hi0) = make_uint4(pack_bf(gh[0],gh[1]),pack_bf(gh[2],gh[3]),pack_bf(gh[4],gh[5]),pack_bf(gh[6],gh[7]));
            *(uint4*)(stB + offB_hi1) = make_uint4(pack_bf(gh[8],gh[9]),pack_bf(gh[10],gh[11]),pack_bf(gh[12],gh[13]),pack_bf(gh[14],gh[15]));
            *(uint4*)(stB + offB_lo0) = make_uint4(pack_bf(g[0]-gh[0],g[1]-gh[1]),pack_bf(g[2]-gh[2],g[3]-gh[3]),
                                                   pack_bf(g[4]-gh[4],g[5]-gh[5]),pack_bf(g[6]-gh[6],g[7]-gh[7]));
            *(uint4*)(stB + offB_lo1) = make_uint4(pack_bf(g[8]-gh[8],g[9]-gh[9]),pack_bf(g[10]-gh[10],g[11]-gh[11]),
                                                   pack_bf(g[12]-gh[12],g[13]-gh[13]),pack_bf(g[14]-gh[14],g[15]-gh[15]));
        }
        // ---- LDG chunk i+2 into freed buffer ----
        if (i + 2 < NC) {
            #pragma unroll
            for (int q = 0; q < 2; ++q) bufA[cur][q] = *(const float4*)(Ap + (i + 2) * KC + q * 4);
            #pragma unroll
            for (int q = 0; q < 4; ++q) bufB[cur][q] = *(const float4*)(Bp + (i + 2) * KC + q * 4);
        }
        // ---- compute on stage cur ----
        const uint32_t baseA = sb + cur * A_STG;
        const uint32_t baseB = sb + 16384 + cur * B_STG;
        #pragma unroll
        for (int s = 0; s < 2; ++s) {
            uint32_t ah[2][4], al[2][4];
            uint32_t bh[4][2], bl[4][2];
            #pragma unroll
            for (int f = 0; f < 2; ++f) {
                ldsm4(ah[f], baseA + aoff[0][s][f]);
                ldsm4(al[f], baseA + aoff[1][s][f]);
            }
            #pragma unroll
            for (int pr = 0; pr < 2; ++pr) {
                uint32_t t[4];
                ldsm4(t, baseB + boff[0][s][pr]);
                bh[2*pr][0]=t[0]; bh[2*pr][1]=t[1]; bh[2*pr+1][0]=t[2]; bh[2*pr+1][1]=t[3];
                ldsm4(t, baseB + boff[1][s][pr]);
                bl[2*pr][0]=t[0]; bl[2*pr][1]=t[1]; bl[2*pr+1][0]=t[2]; bl[2*pr+1][1]=t[3];
            }
            #pragma unroll
            for (int f = 0; f < 2; ++f)
                #pragma unroll
                for (int j = 0; j < 4; ++j) {
                    mma16816(acc[f][j], ah[f], bh[j]);   // hh
                    mma16816(acc[f][j], al[f], bh[j]);   // lh
                    mma16816(acc[f][j], ah[f], bl[j]);   // hl
                }
        }
        __syncthreads();
    }

    // ---- epilogue: stage to smem, coalesced write ----
    float* so = (float*)sm;                     // 64 x 129
    #pragma unroll
    for (int i2 = 0; i2 < 2; ++i2)
        #pragma unroll
        for (int j = 0; j < 4; ++j)
            #pragma unroll
            for (int r = 0; r < 4; ++r) {
                int row = warp_m * 32 + i2 * 16 + (lane >> 2) + ((r >> 1) << 3);
                int col = warp_n * 32 + j * 8 + ((lane & 3) << 1) + (r & 1);
                so[row * 129 + col] = acc[i2][j][r];
            }
    __syncthreads();

    if (!TRANSOUT) {
        #pragma unroll
        for (int it = 0; it < 8; ++it) {
            int idx = tid + 256 * it;
            int row = idx >> 5, q = idx & 31;
            float o[4];
            #pragma unroll
            for (int u = 0; u < 4; ++u) {
                float v = so[row * 129 + q * 4 + u];
                if (BIAS) v += __ldg(bias + n0 + q * 4 + u);
                if (GELU) v = gelu_f(v);
                o[u] = v;
            }
            *(float4*)(C + (size_t)(m0 + row) * ldc + n0 + q * 4) = *(const float4*)o;
        }
    } else {
        #pragma unroll
        for (int it = 0; it < 8; ++it) {
            int idx = tid + 256 * it;
            int n = idx >> 4, q = idx & 15;
            float bv = BIAS ? __ldg(bias + n0 + n) : 0.f;
            float o[4];
            #pragma unroll
            for (int u = 0; u < 4; ++u) {
                float v = so[(q * 4 + u) * 129 + n] + bv;
                if (GELU) v = gelu_f(v);
                o[u] = v;
            }
            *(float4*)(C + (size_t)(n0 + n) * ldc + m0 + q * 4) = *(const float4*)o;
        }
    }
}

// ---------------- 1) weight net ----------------
__global__ void weight_kernel(const float* __restrict__ w1, const float* __restrict__ b1,
                              const float* __restrict__ w2, const float* __restrict__ b2) {
    int l = threadIdx.x;
    if (l >= NLAG) return;
    float lag = (float)(l - QLAG);
    float acc = b2[0];
    #pragma unroll 8
    for (int j = 0; j < 64; ++j) acc += gelu_f(lag * w1[j] + b1[j]) * w2[j];
    g_w[l] = acc;
}

// ---------------- 2) center rows; copy X into Z left half ----------------
__global__ void center_kernel(const float* __restrict__ X) {
    int r = blockIdx.x, tid = threadIdx.x;
    const float4* xr = (const float4*)(X + (size_t)r * DDIM);
    float4 v[4]; float s = 0.f;
    #pragma unroll
    for (int i = 0; i < 4; ++i) {
        v[i] = xr[tid + 256 * i];
        s += v[i].x + v[i].y + v[i].z + v[i].w;
    }
    __shared__ float red[256];
    red[tid] = s; __syncthreads();
    for (int off = 128; off > 0; off >>= 1) {
        if (tid < off) red[tid] += red[tid + off];
        __syncthreads();
    }
    float mean = red[0] * (1.0f / DDIM);
    float4* xc = (float4*)(g_Xc + (size_t)r * DDIM);
    float4* zz = (float4*)(g_Z + (size_t)r * CIN);
    #pragma unroll
    for (int i = 0; i < 4; ++i) {
        float4 t = v[i];
        zz[tid + 256 * i] = t;
        t.x -= mean; t.y -= mean; t.z -= mean; t.w -= mean;
        xc[tid + 256 * i] = t;
    }
}

// ---------------- transpose X -> Xt[4096,256] ----------------
__global__ void transpose_kernel(const float* __restrict__ X, float* __restrict__ XT) {
    __shared__ float t[32][33];
    int bx = blockIdx.x * 32;
    int by = blockIdx.y * 32;
    int x = threadIdx.x, y = threadIdx.y;
    #pragma unroll
    for (int j = 0; j < 32; j += 8)
        t[y + j][x] = X[(size_t)(by + y + j) * DDIM + bx + x];
    __syncthreads();
    #pragma unroll
    for (int j = 0; j < 32; j += 8)
        XT[(size_t)(bx + y + j) * NROWS + by + x] = t[x][y + j];
}

// ---------------- 3) FIR ----------------
__global__ void fir_kernel() {
    __shared__ float sbuf[DDIM + 2 * QLAG];
    __shared__ float ws[NLAG];
    int r = blockIdx.x, tid = threadIdx.x;
    if (tid < NLAG) ws[tid] = g_w[tid];
    if (tid < QLAG) { sbuf[tid] = 0.f; sbuf[DDIM + QLAG + tid] = 0.f; }
    const float4* xc = (const float4*)(g_Xc + (size_t)r * DDIM);
    #pragma unroll
    for (int i = 0; i < 4; ++i) {
        float4 v = xc[tid + 256 * i];
        *((float4*)&sbuf[QLAG + (tid + 256 * i) * 4]) = v;
    }
    __syncthreads();
    float acc[16];
    #pragma unroll
    for (int s = 0; s < 16; ++s) acc[s] = 0.f;
    for (int i = 0; i < NLAG; ++i) {
        float wv = ws[i];
        #pragma unroll
        for (int s = 0; s < 16; ++s) acc[s] += wv * sbuf[tid + 256 * s + i];
    }
    float* y = g_Y + (size_t)r * DDIM;
    #pragma unroll
    for (int s = 0; s < 16; ++s) y[tid + 256 * s] = acc[s];
}

// ---------------- 4) cov partials (fp32 split-K) ----------------
__global__ void __launch_bounds__(256) cov_kernel() {
    const int BM = 64, BN = 64, BK = 16, PA = 4;
    __shared__ float As[2][BK][BM + PA];
    __shared__ float Bs[2][BK][BN + PA];
    int tid = threadIdx.x;
    int m0 = blockIdx.y * BM, n0 = blockIdx.x * BN;
    int k0 = blockIdx.z * (DDIM / SPLITK);
    int am = tid >> 2, ak = (tid & 3) << 2;
    int ty = tid >> 4, tx = tid & 15;
    const float* Ap = g_Xc + (size_t)(m0 + am) * DDIM + k0 + ak;
    const float* Bp = g_Y  + (size_t)(n0 + am) * DDIM + k0 + ak;
    float acc[4][4];
    #pragma unroll
    for (int i = 0; i < 4; ++i)
        #pragma unroll
        for (int j = 0; j < 4; ++j) acc[i][j] = 0.f;
    float4 ra = *(const float4*)Ap, rb = *(const float4*)Bp;
    As[0][ak+0][am]=ra.x; As[0][ak+1][am]=ra.y; As[0][ak+2][am]=ra.z; As[0][ak+3][am]=ra.w;
    Bs[0][ak+0][am]=rb.x; Bs[0][ak+1][am]=rb.y; Bs[0][ak+2][am]=rb.z; Bs[0][ak+3][am]=rb.w;
    __syncthreads();
    const int NKT = (DDIM / SPLITK) / BK;
    for (int kt = 0; kt < NKT; ++kt) {
        int cur = kt & 1;
        bool more = (kt + 1 < NKT);
        if (more) { ra = *(const float4*)(Ap + (kt+1)*BK); rb = *(const float4*)(Bp + (kt+1)*BK); }
        #pragma unroll
        for (int k = 0; k < BK; ++k) {
            float a[4], b[4];
            *(float4*)a = *(const float4*)(&As[cur][k][ty << 2]);
            *(float4*)b = *(const float4*)(&Bs[cur][k][tx << 2]);
            #pragma unroll
            for (int i = 0; i < 4; ++i)
                #pragma unroll
                for (int j = 0; j < 4; ++j) acc[i][j] += a[i] * b[j];
        }
        if (more) {
            int nx = cur ^ 1;
            As[nx][ak+0][am]=ra.x; As[nx][ak+1][am]=ra.y; As[nx][ak+2][am]=ra.z; As[nx][ak+3][am]=ra.w;
            Bs[nx][ak+0][am]=rb.x; Bs[nx][ak+1][am]=rb.y; Bs[nx][ak+2][am]=rb.z; Bs[nx][ak+3][am]=rb.w;
        }
        __syncthreads();
    }
    float* outp = g_covp + (size_t)blockIdx.z * NROWS * NROWS;
    #pragma unroll
    for (int i = 0; i < 4; ++i) {
        float* cp = outp + (size_t)(m0 + (ty << 2) + i) * NROWS + n0 + (tx << 2);
        *(float4*)cp = make_float4(acc[i][0], acc[i][1], acc[i][2], acc[i][3]);
    }
}

__global__ void cov_reduce() {
    int i = blockIdx.x * blockDim.x + threadIdx.x;
    float s = 0.f;
    #pragma unroll
    for (int z = 0; z < SPLITK; ++z) s += g_covp[z * (NROWS * NROWS) + i];
    g_cov[i] = s * (1.0f / DDIM);
}

// ---------------- launch ----------------
extern "C" void kernel_launch(void* const* d_in, const int* in_sizes, int n_in,
                              void* d_out, int out_size) {
    const float* X     = (const float*)d_in[0];
    const float* wn_w1 = (const float*)d_in[1];
    const float* wn_b1 = (const float*)d_in[2];
    const float* wn_w2 = (const float*)d_in[3];
    const float* wn_b2 = (const float*)d_in[4];
    const float* fc1_w = (const float*)d_in[5];
    const float* fc1_b = (const float*)d_in[6];
    const float* fc2_w = (const float*)d_in[7];
    const float* fc2_b = (const float*)d_in[8];
    const float* fc3_w = (const float*)d_in[9];
    const float* fc3_b = (const float*)d_in[10];
    const float* proj  = (const float*)d_in[11];
    float* out = (float*)d_out;

    float *pZ, *pcov, *po1, *po2, *po3t, *pXt;
    cudaGetSymbolAddress((void**)&pZ,   g_Z);
    cudaGetSymbolAddress((void**)&pcov, g_cov);
    cudaGetSymbolAddress((void**)&po1,  g_o1);
    cudaGetSymbolAddress((void**)&po2,  g_o2);
    cudaGetSymbolAddress((void**)&po3t, g_o3t);
    cudaGetSymbolAddress((void**)&pXt,  g_Xt);

    weight_kernel<<<1, NLAG>>>(wn_w1, wn_b1, wn_w2, wn_b2);
    center_kernel<<<NROWS, 256>>>(X);
    transpose_kernel<<<dim3(DDIM / 32, NROWS / 32), dim3(32, 8)>>>(X, pXt);
    fir_kernel<<<NROWS, 256>>>();
    cov_kernel<<<dim3(NROWS / 64, NROWS / 64, SPLITK), 256>>>();
    cov_reduce<<<(NROWS * NROWS) / 256, 256>>>();

    // cov_inter = cov @ X  (NT with B = X^T) -> Z[:, DDIM:]
    hmma_gemm<false, false, false><<<dim3(DDIM / 128, NROWS / 64), 256>>>(
        pcov, pXt, pZ + DDIM, nullptr, NROWS, NROWS, NROWS, CIN);
    // fc1: gelu(Z @ fc1_w^T + b)
    hmma_gemm<true, true, false><<<dim3(HID / 128, NROWS / 64), 256>>>(
        pZ, fc1_w, po1, fc1_b, CIN, CIN, CIN, HID);
    // fc2: gelu(o1 @ fc2_w^T + b)
    hmma_gemm<true, true, false><<<dim3(HID / 128, NROWS / 64), 256>>>(
        po1, fc2_w, po2, fc2_b, HID, HID, HID, HID);
    // fc3: o2 @ fc3_w^T + b -> o3t[4096, 256] (transposed)
    hmma_gemm<true, false, true><<<dim3(HID / 128, NROWS / 64), 256>>>(
        po2, fc3_w, po3t, fc3_b, HID, HID, HID, NROWS);
    // out = proj @ o3  (NT: A=proj[512,256], B=o3t[4096,256])
    hmma_gemm<false, false, false><<<dim3(HID / 128, Y0DIM / 64), 256>>>(
        proj, po3t, out, nullptr, NROWS, NROWS, NROWS, HID);
}

// round 6
// speedup vs baseline: 3.1500x; 1.9740x over previous
#include <cuda_runtime.h>
#include <cuda_bf16.h>
#include <math.h>
#include <cstdint>

#define NROWS 256
#define DDIM  4096
#define CIN   8192
#define HID   4096
#define Y0DIM 512
#define QLAG  64
#define NLAG  129
#define SPLITK 8

// ---------------- scratch (device globals; no allocations allowed) ----------------
__device__ float g_w[NLAG];
__device__ float g_Xc[NROWS * DDIM];
__device__ float g_Y[NROWS * DDIM];
__device__ float g_covpart[SPLITK * NROWS * NROWS];

// packed operands: per 32-k chunk, per row: 128B = [hi bf16 x32 | lo bf16 x32]
__device__ __align__(128) char g_Wp1[(size_t)HID * CIN * 4];     // fc1_w packed
__device__ __align__(128) char g_Wp2[(size_t)HID * HID * 4];     // fc2_w packed
__device__ __align__(128) char g_Wp3[(size_t)HID * HID * 4];     // fc3_w packed
__device__ __align__(128) char g_Pp [(size_t)Y0DIM * NROWS * 4]; // proj packed
__device__ __align__(128) char g_Zp [(size_t)NROWS * CIN * 4];   // [X | cov@X] packed
__device__ __align__(128) char g_o1p[(size_t)NROWS * HID * 4];
__device__ __align__(128) char g_o2p[(size_t)NROWS * HID * 4];
__device__ __align__(128) char g_o3tp[(size_t)HID * NROWS * 4];  // fc3 out transposed packed
__device__ __align__(128) char g_Xtp[(size_t)DDIM * NROWS * 4];  // X^T packed
__device__ __align__(128) char g_Cp [(size_t)NROWS * NROWS * 4]; // cov packed

__device__ __forceinline__ float gelu_f(float x) {
    return 0.5f * x * (1.0f + erff(x * 0.70710678118654752440f));
}
__device__ __forceinline__ uint32_t smem_u32(const void* p) {
    uint32_t a;
    asm("{ .reg .u64 t; cvta.to.shared.u64 t, %1; cvt.u32.u64 %0, t; }" : "=r"(a) : "l"(p));
    return a;
}
__device__ __forceinline__ void ldsm4(uint32_t* r, uint32_t addr) {
    asm volatile("ldmatrix.sync.aligned.m8n8.x4.shared.b16 {%0,%1,%2,%3}, [%4];"
        : "=r"(r[0]), "=r"(r[1]), "=r"(r[2]), "=r"(r[3]) : "r"(addr));
}
__device__ __forceinline__ void mma16816(float* c, const uint32_t* a, const uint32_t* b) {
    asm volatile(
        "mma.sync.aligned.m16n8k16.row.col.f32.bf16.bf16.f32 "
        "{%0,%1,%2,%3}, {%4,%5,%6,%7}, {%8,%9}, {%0,%1,%2,%3};"
        : "+f"(c[0]), "+f"(c[1]), "+f"(c[2]), "+f"(c[3])
        : "r"(a[0]), "r"(a[1]), "r"(a[2]), "r"(a[3]), "r"(b[0]), "r"(b[1]));
}
__device__ __forceinline__ uint32_t pack_bf(float a, float b) {
    __nv_bfloat162 t;
    t.x = __float2bfloat16(a);
    t.y = __float2bfloat16(b);
    return *reinterpret_cast<uint32_t*>(&t);
}
__device__ __forceinline__ float bf_hi(float x) {
    return __bfloat162float(__float2bfloat16(x));
}
__device__ __forceinline__ uint32_t swz(uint32_t off) {
    return off ^ (((off >> 7) & 7) << 4);
}
__device__ __forceinline__ void cp16(uint32_t d, const void* s) {
    asm volatile("cp.async.cg.shared.global [%0], [%1], 16;" :: "r"(d), "l"(s) : "memory");
}
#define CP_COMMIT() asm volatile("cp.async.commit_group;" ::: "memory")
#define CP_WAIT2()  asm volatile("cp.async.wait_group 2;" ::: "memory")

// pack 8 fp32 -> hi uint4 (8 bf16) + lo uint4
__device__ __forceinline__ void pack8(const float* f, uint4& hi, uint4& lo) {
    float h[8];
    #pragma unroll
    for (int u = 0; u < 8; ++u) h[u] = bf_hi(f[u]);
    hi = make_uint4(pack_bf(h[0], h[1]), pack_bf(h[2], h[3]),
                    pack_bf(h[4], h[5]), pack_bf(h[6], h[7]));
    lo = make_uint4(pack_bf(f[0]-h[0], f[1]-h[1]), pack_bf(f[2]-h[2], f[3]-h[3]),
                    pack_bf(f[4]-h[4], f[5]-h[5]), pack_bf(f[6]-h[6], f[7]-h[7]));
}

// ====================== pipelined HMMA bf16 3-split NT GEMM ======================
// Operands pre-packed. BM=64, BN=128, chunk=32 k. 4-stage cp.async.
// OMODE: 0 = fp32 row-major out (ldOut=ldc); 1 = packed out (ldOut=Rout, kbase);
//        2 = packed transposed out (ldOut=row count of transposed tensor)
#define NSTAGE 4
#define A_ST 8192
#define B_ST 16384
#define GEMM_SMEM (NSTAGE * (A_ST + B_ST))   // 96KB

template <int OMODE, bool BIAS, bool GELU>
__global__ void __launch_bounds__(256) gemm_k(
    const char* __restrict__ Ap, const char* __restrict__ Bp,
    void* __restrict__ Cout, const float* __restrict__ bias,
    int NC, int RA, int RB, int ldOut, int kbase)
{
    extern __shared__ __align__(128) char dsm[];
    const uint32_t sb = smem_u32(dsm);
    const int tid = threadIdx.x;
    const int lane = tid & 31, wid = tid >> 5;
    const int warp_m = wid >> 2, warp_n = wid & 3;
    const int m0 = blockIdx.y * 64, n0 = blockIdx.x * 128;

    const uint32_t dA0 = swz(tid * 16), dA1 = swz((tid + 256) * 16);
    uint32_t dB[4];
    #pragma unroll
    for (int j = 0; j < 4; ++j) dB[j] = swz((tid + 256 * j) * 16);

    // ldmatrix offsets: [plane][kstep][frag]
    uint32_t aoff[2][2][2], boff[2][2][2];
    #pragma unroll
    for (int p = 0; p < 2; ++p)
        #pragma unroll
        for (int s = 0; s < 2; ++s)
            #pragma unroll
            for (int f = 0; f < 2; ++f) {
                int rowA = warp_m * 32 + f * 16 + (lane & 15);
                aoff[p][s][f] = swz((uint32_t)rowA * 128 + p * 64 + s * 32 + ((lane >> 4) << 4));
                int rowB = warp_n * 32 + f * 16 + (((lane >> 4) & 1) << 3) + (lane & 7);
                boff[p][s][f] = swz((uint32_t)rowB * 128 + p * 64 + s * 32 + (((lane >> 3) & 1) << 4));
            }

    float acc[2][4][4];
    #pragma unroll
    for (int i = 0; i < 2; ++i)
        #pragma unroll
        for (int j = 0; j < 4; ++j)
            #pragma unroll
            for (int r = 0; r < 4; ++r) acc[i][j][r] = 0.f;

    auto issue_stage = [&](int ic, int s) {
        const char* a = Ap + (((size_t)ic * RA + m0) << 7);
        const char* b = Bp + (((size_t)ic * RB + n0) << 7);
        uint32_t sA = sb + s * A_ST;
        uint32_t sB = sb + NSTAGE * A_ST + s * B_ST;
        cp16(sA + dA0, a + (size_t)tid * 16);
        cp16(sA + dA1, a + (size_t)(tid + 256) * 16);
        #pragma unroll
        for (int j = 0; j < 4; ++j) cp16(sB + dB[j], b + (size_t)(tid + 256 * j) * 16);
    };

    const int npro = NC < 3 ? NC : 3;
    for (int s = 0; s < npro; ++s) { issue_stage(s, s); CP_COMMIT(); }

    for (int i = 0; i < NC; ++i) {
        CP_WAIT2();
        __syncthreads();
        if (i + 3 < NC) { issue_stage(i + 3, (i + 3) & 3); CP_COMMIT(); }

        const uint32_t baseA = sb + (i & 3) * A_ST;
        const uint32_t baseB = sb + NSTAGE * A_ST + (i & 3) * B_ST;
        #pragma unroll
        for (int s = 0; s < 2; ++s) {
            uint32_t ah[2][4], al[2][4], bh[4][2], bl[4][2];
            #pragma unroll
            for (int f = 0; f < 2; ++f) {
                ldsm4(ah[f], baseA + aoff[0][s][f]);
                ldsm4(al[f], baseA + aoff[1][s][f]);
            }
            #pragma unroll
            for (int pr = 0; pr < 2; ++pr) {
                uint32_t t[4];
                ldsm4(t, baseB + boff[0][s][pr]);
                bh[2*pr][0]=t[0]; bh[2*pr][1]=t[1]; bh[2*pr+1][0]=t[2]; bh[2*pr+1][1]=t[3];
                ldsm4(t, baseB + boff[1][s][pr]);
                bl[2*pr][0]=t[0]; bl[2*pr][1]=t[1]; bl[2*pr+1][0]=t[2]; bl[2*pr+1][1]=t[3];
            }
            #pragma unroll
            for (int f = 0; f < 2; ++f)
                #pragma unroll
                for (int j = 0; j < 4; ++j) {
                    mma16816(acc[f][j], ah[f], bh[j]);   // hh
                    mma16816(acc[f][j], al[f], bh[j]);   // lh
                    mma16816(acc[f][j], ah[f], bl[j]);   // hl
                }
        }
    }
    __syncthreads();

    // ---- stage accumulators into smem ----
    float* so = (float*)dsm;                     // 64 x 129
    #pragma unroll
    for (int i2 = 0; i2 < 2; ++i2)
        #pragma unroll
        for (int j = 0; j < 4; ++j)
            #pragma unroll
            for (int r = 0; r < 4; ++r) {
                int row = warp_m * 32 + i2 * 16 + (lane >> 2) + ((r >> 1) << 3);
                int col = warp_n * 32 + j * 8 + ((lane & 3) << 1) + (r & 1);
                so[row * 129 + col] = acc[i2][j][r];
            }
    __syncthreads();

    if (OMODE == 0) {
        float* C = (float*)Cout;
        #pragma unroll
        for (int it = 0; it < 8; ++it) {
            int idx = tid + 256 * it;
            int row = idx >> 5, q = idx & 31;
            float o[4];
            #pragma unroll
            for (int u = 0; u < 4; ++u) {
                float v = so[row * 129 + q * 4 + u];
                if (BIAS) v += __ldg(bias + n0 + q * 4 + u);
                if (GELU) v = gelu_f(v);
                o[u] = v;
            }
            *(float4*)(C + (size_t)(m0 + row) * ldOut + n0 + q * 4) = *(const float4*)o;
        }
    } else if (OMODE == 1) {
        char* dst = (char*)Cout;
        #pragma unroll
        for (int it = 0; it < 4; ++it) {
            int task = tid + 256 * it;               // 1024 tasks: 64 m x 16 c-groups
            int m = task >> 4, c = (task & 15) * 8;
            float v[8];
            #pragma unroll
            for (int u = 0; u < 8; ++u) {
                float x = so[m * 129 + c + u];
                if (BIAS) x += __ldg(bias + n0 + c + u);
                if (GELU) x = gelu_f(x);
                v[u] = x;
            }
            uint4 hi, lo;
            pack8(v, hi, lo);
            int kk = kbase + n0 + c;
            size_t base = (((size_t)(kk >> 5) * ldOut + m0 + m) << 7) + ((kk & 31) >> 3) * 16;
            *(uint4*)(dst + base) = hi;
            *(uint4*)(dst + base + 64) = lo;
        }
    } else {
        // packed transposed: out rows = n-global, k = m-global
        char* dst = (char*)Cout;
        int h = tid >> 7, n = tid & 127;
        float bv = BIAS ? __ldg(bias + n0 + n) : 0.f;
        float v[32];
        #pragma unroll
        for (int i2 = 0; i2 < 32; ++i2) {
            float x = so[(h * 32 + i2) * 129 + n] + bv;
            if (GELU) x = gelu_f(x);
            v[i2] = x;
        }
        size_t base = (((size_t)((m0 >> 5) + h) * ldOut + n0 + n) << 7);
        #pragma unroll
        for (int q = 0; q < 4; ++q) {
            uint4 hi, lo;
            pack8(v + 8 * q, hi, lo);
            *(uint4*)(dst + base + q * 16) = hi;
            *(uint4*)(dst + base + 64 + q * 16) = lo;
        }
    }
}

// ---------------- generic fp32 -> packed converter ----------------
__global__ void pack_kernel(const float* __restrict__ src, char* __restrict__ dst,
                            int R, int K, int total) {
    int idx = blockIdx.x * 256 + threadIdx.x;
    if (idx >= total) return;
    int kg = K >> 3;
    int r = idx / kg;
    int koff = (idx - r * kg) << 3;
    float f[8];
    *(float4*)f       = *(const float4*)(src + (size_t)r * K + koff);
    *(float4*)(f + 4) = *(const float4*)(src + (size_t)r * K + koff + 4);
    uint4 hi, lo;
    pack8(f, hi, lo);
    size_t base = (((size_t)(koff >> 5) * R + r) << 7) + ((koff & 31) >> 3) * 16;
    *(uint4*)(dst + base) = hi;
    *(uint4*)(dst + base + 64) = lo;
}

// ---------------- 1) weight net ----------------
__global__ void weight_kernel(const float* __restrict__ w1, const float* __restrict__ b1,
                              const float* __restrict__ w2, const float* __restrict__ b2) {
    int l = threadIdx.x;
    if (l >= NLAG) return;
    float lag = (float)(l - QLAG);
    float acc = b2[0];
    #pragma unroll 8
    for (int j = 0; j < 64; ++j) acc += gelu_f(lag * w1[j] + b1[j]) * w2[j];
    g_w[l] = acc;
}

// ---------------- 2) center rows; emit packed X into Zp left half ----------------
__global__ void center_kernel(const float* __restrict__ X, char* __restrict__ Zp) {
    int r = blockIdx.x, tid = threadIdx.x;
    const float* xr = X + (size_t)r * DDIM;
    float f0[8], f1[8];
    int k0 = tid * 8, k1 = 2048 + tid * 8;
    *(float4*)f0       = *(const float4*)(xr + k0);
    *(float4*)(f0 + 4) = *(const float4*)(xr + k0 + 4);
    *(float4*)f1       = *(const float4*)(xr + k1);
    *(float4*)(f1 + 4) = *(const float4*)(xr + k1 + 4);
    float s = 0.f;
    #pragma unroll
    for (int u = 0; u < 8; ++u) s += f0[u] + f1[u];
    __shared__ float red[256];
    red[tid] = s; __syncthreads();
    for (int off = 128; off > 0; off >>= 1) {
        if (tid < off) red[tid] += red[tid + off];
        __syncthreads();
    }
    float mean = red[0] * (1.0f / DDIM);
    // packed raw X
    uint4 hi, lo;
    pack8(f0, hi, lo);
    size_t b0 = (((size_t)(k0 >> 5) * NROWS + r) << 7) + ((k0 & 31) >> 3) * 16;
    *(uint4*)(Zp + b0) = hi; *(uint4*)(Zp + b0 + 64) = lo;
    pack8(f1, hi, lo);
    size_t b1 = (((size_t)(k1 >> 5) * NROWS + r) << 7) + ((k1 & 31) >> 3) * 16;
    *(uint4*)(Zp + b1) = hi; *(uint4*)(Zp + b1 + 64) = lo;
    // centered fp32 for cov path
    float* xc = g_Xc + (size_t)r * DDIM;
    #pragma unroll
    for (int u = 0; u < 8; ++u) { f0[u] -= mean; f1[u] -= mean; }
    *(float4*)(xc + k0)     = *(float4*)f0;
    *(float4*)(xc + k0 + 4) = *(float4*)(f0 + 4);
    *(float4*)(xc + k1)     = *(float4*)f1;
    *(float4*)(xc + k1 + 4) = *(float4*)(f1 + 4);
}

// ---------------- transpose X -> packed Xt [DDIM rows, K=NROWS] ----------------
__global__ void transpose_kernel(const float* __restrict__ X, char* __restrict__ XTp) {
    __shared__ float t[32][33];
    int bx = blockIdx.x * 32;    // col of X = row of Xt
    int by = blockIdx.y * 32;    // row of X = k of Xt
    int x = threadIdx.x, y = threadIdx.y;
    #pragma unroll
    for (int j = 0; j < 32; j += 8)
        t[y + j][x] = X[(size_t)(by + y + j) * DDIM + bx + x];
    __syncthreads();
    int tt = y * 32 + x;
    if (tt < 128) {
        int rr = tt >> 2, grp = tt & 3;
        float v[8];
        #pragma unroll
        for (int u = 0; u < 8; ++u) v[u] = t[grp * 8 + u][rr];
        uint4 hi, lo;
        pack8(v, hi, lo);
        size_t base = (((size_t)(by >> 5) * DDIM + bx + rr) << 7) + grp * 16;
        *(uint4*)(XTp + base) = hi;
        *(uint4*)(XTp + base + 64) = lo;
    }
}

// ---------------- 3) FIR ----------------
__global__ void fir_kernel() {
    __shared__ float sbuf[DDIM + 2 * QLAG];
    __shared__ float ws[NLAG];
    int r = blockIdx.x, tid = threadIdx.x;
    if (tid < NLAG) ws[tid] = g_w[tid];
    if (tid < QLAG) { sbuf[tid] = 0.f; sbuf[DDIM + QLAG + tid] = 0.f; }
    const float4* xc = (const float4*)(g_Xc + (size_t)r * DDIM);
    #pragma unroll
    for (int i = 0; i < 4; ++i) {
        float4 v = xc[tid + 256 * i];
        *((float4*)&sbuf[QLAG + (tid + 256 * i) * 4]) = v;
    }
    __syncthreads();
    float acc[16];
    #pragma unroll
    for (int s = 0; s < 16; ++s) acc[s] = 0.f;
    for (int i = 0; i < NLAG; ++i) {
        float wv = ws[i];
        #pragma unroll
        for (int s = 0; s < 16; ++s) acc[s] += wv * sbuf[tid + 256 * s + i];
    }
    float* y = g_Y + (size_t)r * DDIM;
    #pragma unroll
    for (int s = 0; s < 16; ++s) y[tid + 256 * s] = acc[s];
}

// ---------------- 4) cov partials (fp32 split-K) ----------------
__global__ void __launch_bounds__(256) cov_kernel() {
    const int BM = 64, BN = 64, BK = 16, PA = 4;
    __shared__ float As[2][BK][BM + PA];
    __shared__ float Bs[2][BK][BN + PA];
    int tid = threadIdx.x;
    int m0 = blockIdx.y * BM, n0 = blockIdx.x * BN;
    int k0 = blockIdx.z * (DDIM / SPLITK);
    int am = tid >> 2, ak = (tid & 3) << 2;
    int ty = tid >> 4, tx = tid & 15;
    const float* Ap = g_Xc + (size_t)(m0 + am) * DDIM + k0 + ak;
    const float* Bp = g_Y  + (size_t)(n0 + am) * DDIM + k0 + ak;
    float acc[4][4];
    #pragma unroll
    for (int i = 0; i < 4; ++i)
        #pragma unroll
        for (int j = 0; j < 4; ++j) acc[i][j] = 0.f;
    float4 ra = *(const float4*)Ap, rb = *(const float4*)Bp;
    As[0][ak+0][am]=ra.x; As[0][ak+1][am]=ra.y; As[0][ak+2][am]=ra.z; As[0][ak+3][am]=ra.w;
    Bs[0][ak+0][am]=rb.x; Bs[0][ak+1][am]=rb.y; Bs[0][ak+2][am]=rb.z; Bs[0][ak+3][am]=rb.w;
    __syncthreads();
    const int NKT = (DDIM / SPLITK) / BK;
    for (int kt = 0; kt < NKT; ++kt) {
        int cur = kt & 1;
        bool more = (kt + 1 < NKT);
        if (more) { ra = *(const float4*)(Ap + (kt+1)*BK); rb = *(const float4*)(Bp + (kt+1)*BK); }
        #pragma unroll
        for (int k = 0; k < BK; ++k) {
            float a[4], b[4];
            *(float4*)a = *(const float4*)(&As[cur][k][ty << 2]);
            *(float4*)b = *(const float4*)(&Bs[cur][k][tx << 2]);
            #pragma unroll
            for (int i = 0; i < 4; ++i)
                #pragma unroll
                for (int j = 0; j < 4; ++j) acc[i][j] += a[i] * b[j];
        }
        if (more) {
            int nx = cur ^ 1;
            As[nx][ak+0][am]=ra.x; As[nx][ak+1][am]=ra.y; As[nx][ak+2][am]=ra.z; As[nx][ak+3][am]=ra.w;
            Bs[nx][ak+0][am]=rb.x; Bs[nx][ak+1][am]=rb.y; Bs[nx][ak+2][am]=rb.z; Bs[nx][ak+3][am]=rb.w;
        }
        __syncthreads();
    }
    float* outp = g_covpart + (size_t)blockIdx.z * NROWS * NROWS;
    #pragma unroll
    for (int i = 0; i < 4; ++i) {
        float* cp = outp + (size_t)(m0 + (ty << 2) + i) * NROWS + n0 + (tx << 2);
        *(float4*)cp = make_float4(acc[i][0], acc[i][1], acc[i][2], acc[i][3]);
    }
}

// cov reduce + pack: 8192 tasks (256 rows x 32 groups of 8)
__global__ void cov_reduce(char* __restrict__ Cp) {
    int idx = blockIdx.x * 256 + threadIdx.x;
    int r = idx >> 5;
    int cg = (idx & 31) << 3;
    float v[8];
    #pragma unroll
    for (int u = 0; u < 8; ++u) v[u] = 0.f;
    #pragma unroll
    for (int z = 0; z < SPLITK; ++z) {
        const float* p = g_covpart + (size_t)z * NROWS * NROWS + (size_t)r * NROWS + cg;
        float4 a = *(const float4*)p, b = *(const float4*)(p + 4);
        v[0]+=a.x; v[1]+=a.y; v[2]+=a.z; v[3]+=a.w;
        v[4]+=b.x; v[5]+=b.y; v[6]+=b.z; v[7]+=b.w;
    }
    #pragma unroll
    for (int u = 0; u < 8; ++u) v[u] *= (1.0f / DDIM);
    uint4 hi, lo;
    pack8(v, hi, lo);
    size_t base = (((size_t)(cg >> 5) * NROWS + r) << 7) + ((cg & 31) >> 3) * 16;
    *(uint4*)(Cp + base) = hi;
    *(uint4*)(Cp + base + 64) = lo;
}

// ---------------- launch ----------------
extern "C" void kernel_launch(void* const* d_in, const int* in_sizes, int n_in,
                              void* d_out, int out_size) {
    const float* X     = (const float*)d_in[0];
    const float* wn_w1 = (const float*)d_in[1];
    const float* wn_b1 = (const float*)d_in[2];
    const float* wn_w2 = (const float*)d_in[3];
    const float* wn_b2 = (const float*)d_in[4];
    const float* fc1_w = (const float*)d_in[5];
    const float* fc1_b = (const float*)d_in[6];
    const float* fc2_w = (const float*)d_in[7];
    const float* fc2_b = (const float*)d_in[8];
    const float* fc3_w = (const float*)d_in[9];
    const float* fc3_b = (const float*)d_in[10];
    const float* proj  = (const float*)d_in[11];
    float* out = (float*)d_out;

    char *pWp1, *pWp2, *pWp3, *pPp, *pZp, *po1p, *po2p, *po3tp, *pXtp, *pCp;
    cudaGetSymbolAddress((void**)&pWp1,  g_Wp1);
    cudaGetSymbolAddress((void**)&pWp2,  g_Wp2);
    cudaGetSymbolAddress((void**)&pWp3,  g_Wp3);
    cudaGetSymbolAddress((void**)&pPp,   g_Pp);
    cudaGetSymbolAddress((void**)&pZp,   g_Zp);
    cudaGetSymbolAddress((void**)&po1p,  g_o1p);
    cudaGetSymbolAddress((void**)&po2p,  g_o2p);
    cudaGetSymbolAddress((void**)&po3tp, g_o3tp);
    cudaGetSymbolAddress((void**)&pXtp,  g_Xtp);
    cudaGetSymbolAddress((void**)&pCp,   g_Cp);

    cudaFuncSetAttribute(gemm_k<0, false, false>, cudaFuncAttributeMaxDynamicSharedMemorySize, GEMM_SMEM);
    cudaFuncSetAttribute(gemm_k<1, false, false>, cudaFuncAttributeMaxDynamicSharedMemorySize, GEMM_SMEM);
    cudaFuncSetAttribute(gemm_k<1, true,  true >, cudaFuncAttributeMaxDynamicSharedMemorySize, GEMM_SMEM);
    cudaFuncSetAttribute(gemm_k<2, true,  false>, cudaFuncAttributeMaxDynamicSharedMemorySize, GEMM_SMEM);

    weight_kernel<<<1, NLAG>>>(wn_w1, wn_b1, wn_w2, wn_b2);
    center_kernel<<<NROWS, 256>>>(X, pZp);
    transpose_kernel<<<dim3(DDIM / 32, NROWS / 32), dim3(32, 8)>>>(X, pXtp);
    fir_kernel<<<NROWS, 256>>>();
    cov_kernel<<<dim3(NROWS / 64, NROWS / 64, SPLITK), 256>>>();
    cov_reduce<<<32, 256>>>(pCp);

    // pack weights + proj
    {
        int t1 = HID * CIN / 8;     // 4M
        pack_kernel<<<(t1 + 255) / 256, 256>>>(fc1_w, pWp1, HID, CIN, t1);
        int t2 = HID * HID / 8;     // 2M
        pack_kernel<<<(t2 + 255) / 256, 256>>>(fc2_w, pWp2, HID, HID, t2);
        pack_kernel<<<(t2 + 255) / 256, 256>>>(fc3_w, pWp3, HID, HID, t2);
        int t3 = Y0DIM * NROWS / 8; // 16K
        pack_kernel<<<(t3 + 255) / 256, 256>>>(proj, pPp, Y0DIM, NROWS, t3);
    }

    // cov_inter = cov @ X -> Zp right half (packed, kbase=DDIM)
    gemm_k<1, false, false><<<dim3(DDIM / 128, NROWS / 64), 256, GEMM_SMEM>>>(
        pCp, pXtp, pZp, nullptr, NROWS / 32, NROWS, DDIM, NROWS, DDIM);
    // fc1: gelu(Z @ fc1_w^T + b) -> o1p
    gemm_k<1, true, true><<<dim3(HID / 128, NROWS / 64), 256, GEMM_SMEM>>>(
        pZp, pWp1, po1p, fc1_b, CIN / 32, NROWS, HID, NROWS, 0);
    // fc2: gelu(o1 @ fc2_w^T + b) -> o2p
    gemm_k<1, true, true><<<dim3(HID / 128, NROWS / 64), 256, GEMM_SMEM>>>(
        po1p, pWp2, po2p, fc2_b, HID / 32, NROWS, HID, NROWS, 0);
    // fc3: o2 @ fc3_w^T + b -> o3tp (packed transposed)
    gemm_k<2, true, false><<<dim3(HID / 128, NROWS / 64), 256, GEMM_SMEM>>>(
        po2p, pWp3, po3tp, fc3_b, HID / 32, NROWS, HID, HID, 0);
    // out = proj @ o3 (NT: A=projp, B=o3tp) -> fp32 out
    gemm_k<0, false, false><<<dim3(HID / 128, Y0DIM / 64), 256, GEMM_SMEM>>>(
        pPp, po3tp, out, nullptr, NROWS / 32, Y0DIM, HID, HID, 0);
}